// round 8
// baseline (speedup 1.0000x reference)
#include <cuda_runtime.h>
#include <math.h>

constexpr int NN = 20000;
constexpr int NE = 320000;
constexpr int T = 4;

__device__ float g_m_buf[NE * 128];  // edge messages, CSR-slot order
__device__ float g_agg[NN * 640];    // 5 aggregators x 128 ch
__device__ float g_scal[NN * 2];     // amp, att
__device__ float g_tow[NN * 128];
__device__ int   g_deg[NN];
__device__ int   g_cur[NN];
__device__ int   g_off[NN + 1];
__device__ int   g_eid[NE];          // slot -> edge (inverse permutation)
__device__ float g_enc[160];         // bond_emb @ enc_w + enc_b  [5][32]
__device__ float g_avg_log;

// ---- packed fp32x2 helpers ----
__device__ __forceinline__ unsigned long long bcast2(float x) {
  unsigned long long r;
  asm("mov.b64 %0, {%1, %1};" : "=l"(r) : "f"(x));
  return r;
}
__device__ __forceinline__ void fma2(unsigned long long& acc,
                                     unsigned long long a, unsigned long long b) {
  asm("fma.rn.f32x2 %0, %1, %2, %0;" : "+l"(acc) : "l"(a), "l"(b));
}
__device__ __forceinline__ void unpack2(unsigned long long v, float& lo, float& hi) {
  asm("mov.b64 {%0, %1}, %2;" : "=f"(lo), "=f"(hi) : "l"(v));
}

template <int KTOT>
__device__ __forceinline__ void tile_mma(
    const float* __restrict__ h0, const float* __restrict__ h1,
    const float* __restrict__ h2, const float* __restrict__ h3,
    const float* __restrict__ wbase, unsigned long long (&acc)[4][2])
{
  const float* hp[4] = {h0, h1, h2, h3};
#pragma unroll 4
  for (int k = 0; k < KTOT; k += 4) {
    ulonglong2 w[4];
#pragma unroll
    for (int kk = 0; kk < 4; kk++)
      w[kk] = *reinterpret_cast<const ulonglong2*>(wbase + (k + kk) * 32);
#pragma unroll
    for (int i = 0; i < 4; i++) {
      float4 h = *reinterpret_cast<const float4*>(hp[i] + k);
      unsigned long long hx = bcast2(h.x), hy = bcast2(h.y);
      unsigned long long hz = bcast2(h.z), hw = bcast2(h.w);
      fma2(acc[i][0], hx, w[0].x); fma2(acc[i][1], hx, w[0].y);
      fma2(acc[i][0], hy, w[1].x); fma2(acc[i][1], hy, w[1].y);
      fma2(acc[i][0], hz, w[2].x); fma2(acc[i][1], hz, w[2].y);
      fma2(acc[i][0], hw, w[3].x); fma2(acc[i][1], hw, w[3].y);
    }
  }
}

__global__ void k_prep(const int* __restrict__ mol_deg,
                       const float* __restrict__ bond_emb,
                       const float* __restrict__ enc_w,
                       const float* __restrict__ enc_b)
{
  __shared__ float rn[128], rd[128];
  int tid = threadIdx.x;
  if (tid < 128) {
    float dv = (float)mol_deg[tid];
    rn[tid] = logf((float)tid + 1.0f) * dv;
    rd[tid] = dv;
  }
  __syncthreads();
  for (int s = 64; s > 0; s >>= 1) {
    if (tid < s) { rn[tid] += rn[tid + s]; rd[tid] += rd[tid + s]; }
    __syncthreads();
  }
  if (tid == 0) g_avg_log = rn[0] / rd[0];
  if (tid < 160) {
    int bb = tid >> 5, f = tid & 31;
    float a = enc_b[f];
    for (int k = 0; k < 128; k++) a += bond_emb[bb * 128 + k] * enc_w[k * 32 + f];
    g_enc[tid] = a;
  }
}

__global__ void k_zero() {
  int i = blockIdx.x * blockDim.x + threadIdx.x;
  if (i < NN) { g_deg[i] = 0; g_cur[i] = 0; }
}

__global__ void k_deg(const int* __restrict__ dst) {
  int e = blockIdx.x * blockDim.x + threadIdx.x;
  if (e < NE) atomicAdd(&g_deg[dst[e]], 1);
}

__global__ void k_scan() {
  extern __shared__ int sdeg[];
  __shared__ int wsum[32];
  const int tid = threadIdx.x, lane = tid & 31, wid = tid >> 5;
  constexpr int CH = 20;
  for (int j = tid; j < 20480; j += 1024) sdeg[j] = (j < NN) ? g_deg[j] : 0;
  __syncthreads();
  const int base = tid * CH;
  int vals[CH];
  int s = 0;
#pragma unroll
  for (int i = 0; i < CH; i++) { vals[i] = sdeg[base + i]; s += vals[i]; }
  int inc = s;
#pragma unroll
  for (int d = 1; d < 32; d <<= 1) {
    int v = __shfl_up_sync(0xffffffffu, inc, d);
    if (lane >= d) inc += v;
  }
  if (lane == 31) wsum[wid] = inc;
  __syncthreads();
  if (wid == 0) {
    int v = wsum[lane];
    int iv = v;
#pragma unroll
    for (int d = 1; d < 32; d <<= 1) {
      int t2 = __shfl_up_sync(0xffffffffu, iv, d);
      if (lane >= d) iv += t2;
    }
    wsum[lane] = iv - v;
  }
  __syncthreads();
  int run = wsum[wid] + inc - s;
#pragma unroll
  for (int i = 0; i < CH; i++) { sdeg[base + i] = run; run += vals[i]; }
  __syncthreads();
  for (int j = tid; j < NN; j += 1024) g_off[j] = sdeg[j];
  if (tid == 1023) g_off[NN] = run;
}

__global__ void k_fill(const int* __restrict__ dst) {
  int e = blockIdx.x * blockDim.x + threadIdx.x;
  if (e < NE) {
    int d = dst[e];
    int sl = g_off[d] + atomicAdd(&g_cur[d], 1);
    g_eid[sl] = e;
  }
}

// ---- edge pre-MLP in SLOT order: sorted dst, sequential m_buf writes -------
struct EdgeSmem {
  float hs[128][36];
  float W1s[96][32];
  float W2s[32][32];
  float ms[128][36];
  float enc_s[160];
  int src_s[128], dst_s[128], bond_s[128];
};

__global__ __launch_bounds__(256) void k_edge(
    const float* __restrict__ x, const int* __restrict__ src,
    const int* __restrict__ dst, const int* __restrict__ bond,
    const float* __restrict__ pre_w1, const float* __restrict__ pre_b1,
    const float* __restrict__ pre_w2, const float* __restrict__ pre_b2)
{
  extern __shared__ __align__(16) char raw[];
  EdgeSmem& s = *reinterpret_cast<EdgeSmem*>(raw);
  const int tid = threadIdx.x, s0 = blockIdx.x * 128;
  if (tid < 128) {
    int e = g_eid[s0 + tid];
    s.src_s[tid]  = src[e];
    s.dst_s[tid]  = dst[e];
    s.bond_s[tid] = bond[e];
  }
  if (tid < 160) s.enc_s[tid] = g_enc[tid];
  const int og = tid & 7, eg = tid >> 3, g0 = og * 4;
  const int c = tid & 31, grp = tid >> 5;

  for (int t = 0; t < T; t++) {
    unsigned long long acc[4][2] = {};
#pragma unroll
    for (int chunk = 0; chunk < 3; chunk++) {
      __syncthreads();
#pragma unroll
      for (int i = 0; i < 16; i++) {
        int e = grp + i * 8;
        float v;
        if (chunk == 0)      v = x[s.dst_s[e] * 128 + t * 32 + c];  // sorted: L1 hits
        else if (chunk == 1) v = x[s.src_s[e] * 128 + t * 32 + c];
        else                 v = s.enc_s[s.bond_s[e] * 32 + c];
        s.hs[e][c] = v;
      }
      if (chunk == 0) {
#pragma unroll
        for (int j = 0; j < 12; j++)
          (&s.W1s[0][0])[tid + j * 256] = pre_w1[t * 3072 + tid + j * 256];
#pragma unroll
        for (int j = 0; j < 4; j++)
          (&s.W2s[0][0])[tid + j * 256] = pre_w2[t * 1024 + tid + j * 256];
      }
      __syncthreads();
      tile_mma<32>(&s.hs[eg][0], &s.hs[eg+32][0], &s.hs[eg+64][0], &s.hs[eg+96][0],
                   &s.W1s[chunk * 32][g0], acc);
    }
#pragma unroll
    for (int i = 0; i < 4; i++) {
      float a0, a1, a2, a3;
      unpack2(acc[i][0], a0, a1); unpack2(acc[i][1], a2, a3);
      float4 v;
      v.x = fmaxf(a0 + pre_b1[t*32 + g0 + 0], 0.f);
      v.y = fmaxf(a1 + pre_b1[t*32 + g0 + 1], 0.f);
      v.z = fmaxf(a2 + pre_b1[t*32 + g0 + 2], 0.f);
      v.w = fmaxf(a3 + pre_b1[t*32 + g0 + 3], 0.f);
      *reinterpret_cast<float4*>(&s.ms[eg + i*32][g0]) = v;
    }
    __syncthreads();
    unsigned long long ac2[4][2] = {};
    tile_mma<32>(&s.ms[eg][0], &s.ms[eg+32][0], &s.ms[eg+64][0], &s.ms[eg+96][0],
                 &s.W2s[0][g0], ac2);
#pragma unroll
    for (int i = 0; i < 4; i++) {
      int sl = s0 + eg + i * 32;           // sequential streaming write
      float a0, a1, a2, a3;
      unpack2(ac2[i][0], a0, a1); unpack2(ac2[i][1], a2, a3);
      float4 v;
      v.x = a0 + pre_b2[t*32 + g0 + 0];
      v.y = a1 + pre_b2[t*32 + g0 + 1];
      v.z = a2 + pre_b2[t*32 + g0 + 2];
      v.w = a3 + pre_b2[t*32 + g0 + 3];
      *reinterpret_cast<float4*>(&g_m_buf[sl * 128 + t * 32 + g0]) = v;
    }
  }
}

// ---- aggregation -> g_agg (5x128) + g_scal ---------------------------------
__global__ void k_agg()
{
  const int n = blockIdx.x, cth = threadIdx.x;
  const int b = g_off[n], d = g_off[n + 1] - b;
  float sum = 0.f, sq = 0.f, mn = 1e30f, mx = -1e30f;
  int i = 0;
  for (; i + 4 <= d; i += 4) {
    float v0 = g_m_buf[(b + i    ) * 128 + cth];
    float v1 = g_m_buf[(b + i + 1) * 128 + cth];
    float v2 = g_m_buf[(b + i + 2) * 128 + cth];
    float v3 = g_m_buf[(b + i + 3) * 128 + cth];
    sum += v0 + v1 + v2 + v3;
    sq += v0*v0 + v1*v1 + v2*v2 + v3*v3;
    mn = fminf(mn, fminf(fminf(v0, v1), fminf(v2, v3)));
    mx = fmaxf(mx, fmaxf(fmaxf(v0, v1), fmaxf(v2, v3)));
  }
  for (; i < d; i++) {
    float v = g_m_buf[(b + i) * 128 + cth];
    sum += v; sq += v * v; mn = fminf(mn, v); mx = fmaxf(mx, v);
  }
  float cnt1 = fmaxf((float)d, 1.f);
  float mean = sum / cnt1;
  float sd = sqrtf(fmaxf(sq / cnt1 - mean * mean, 0.f) + 1e-5f);
  if (d == 0) { mn = 0.f; mx = 0.f; }
  float* ar = &g_agg[n * 640];
  ar[cth] = sum; ar[128 + cth] = mean; ar[256 + cth] = mn;
  ar[384 + cth] = mx; ar[512 + cth] = sd;
  if (cth == 0) {
    float logd = logf(cnt1 + 1.f), al = g_avg_log;
    g_scal[n * 2] = logd / al;
    g_scal[n * 2 + 1] = al / logd;
  }
}

// ---- node post-MLP ---------------------------------------------------------
__global__ __launch_bounds__(256) void k_post(
    const float* __restrict__ x,
    const float* __restrict__ post_w1, const float* __restrict__ post_b1,
    const float* __restrict__ post_w2, const float* __restrict__ post_b2)
{
  __shared__ __align__(16) float fs[128][36];
  __shared__ __align__(16) float Ws[32][32];
  __shared__ __align__(16) float ms2[128][36];
  __shared__ float scal_s[128][2];
  const int tid = threadIdx.x, n0 = blockIdx.x * 128;
  const int og = tid & 7, eg = tid >> 3, g0 = og * 4;
  const int c = tid & 31, grp = tid >> 5;
  if (tid < 128) {
    int node = min(n0 + tid, NN - 1);
    scal_s[tid][0] = g_scal[node * 2];
    scal_s[tid][1] = g_scal[node * 2 + 1];
  }

  for (int t = 0; t < T; t++) {
    unsigned long long acc[4][2] = {};
    for (int kc = 0; kc < 16; kc++) {
      __syncthreads();
#pragma unroll
      for (int i = 0; i < 16; i++) {
        int r = grp + i * 8;
        int node = min(n0 + r, NN - 1);
        float v;
        if (kc == 0) v = x[node * 128 + t * 32 + c];
        else {
          int j = (kc - 1) % 5;
          v = g_agg[node * 640 + j * 128 + t * 32 + c];
          if (kc >= 6) v *= (kc < 11) ? scal_s[r][0] : scal_s[r][1];
        }
        fs[r][c] = v;
      }
#pragma unroll
      for (int j = 0; j < 4; j++)
        (&Ws[0][0])[tid + j * 256] = post_w1[t * 16384 + kc * 1024 + tid + j * 256];
      __syncthreads();
      tile_mma<32>(&fs[eg][0], &fs[eg+32][0], &fs[eg+64][0], &fs[eg+96][0],
                   &Ws[0][g0], acc);
    }
#pragma unroll
    for (int i = 0; i < 4; i++) {
      float a0, a1, a2, a3;
      unpack2(acc[i][0], a0, a1); unpack2(acc[i][1], a2, a3);
      float4 v;
      v.x = fmaxf(a0 + post_b1[t*32 + g0 + 0], 0.f);
      v.y = fmaxf(a1 + post_b1[t*32 + g0 + 1], 0.f);
      v.z = fmaxf(a2 + post_b1[t*32 + g0 + 2], 0.f);
      v.w = fmaxf(a3 + post_b1[t*32 + g0 + 3], 0.f);
      *reinterpret_cast<float4*>(&ms2[eg + i*32][g0]) = v;
    }
    __syncthreads();
#pragma unroll
    for (int j = 0; j < 4; j++)
      (&Ws[0][0])[tid + j * 256] = post_w2[t * 1024 + tid + j * 256];
    __syncthreads();
    unsigned long long ac2[4][2] = {};
    tile_mma<32>(&ms2[eg][0], &ms2[eg+32][0], &ms2[eg+64][0], &ms2[eg+96][0],
                 &Ws[0][g0], ac2);
#pragma unroll
    for (int i = 0; i < 4; i++) {
      int node = n0 + eg + i * 32;
      if (node < NN) {
        float a0, a1, a2, a3;
        unpack2(ac2[i][0], a0, a1); unpack2(ac2[i][1], a2, a3);
        float4 v;
        v.x = a0 + post_b2[t*32 + g0 + 0];
        v.y = a1 + post_b2[t*32 + g0 + 1];
        v.z = a2 + post_b2[t*32 + g0 + 2];
        v.w = a3 + post_b2[t*32 + g0 + 3];
        *reinterpret_cast<float4*>(&g_tow[node * 128 + t * 32 + g0]) = v;
      }
    }
    __syncthreads();
  }
}

// ---- final 128x128 linear --------------------------------------------------
__global__ __launch_bounds__(256) void k_lin(
    const float* __restrict__ lin_w, const float* __restrict__ lin_b,
    float* __restrict__ out)
{
  __shared__ __align__(16) float xs[128][36];
  __shared__ __align__(16) float Ws[32][32];
  const int tid = threadIdx.x, n0 = blockIdx.x * 128;
  const int og = tid & 7, eg = tid >> 3, g0 = og * 4;
  const int c = tid & 31, grp = tid >> 5;

  for (int oc = 0; oc < 4; oc++) {
    unsigned long long acc[4][2] = {};
    for (int kc = 0; kc < 4; kc++) {
      __syncthreads();
#pragma unroll
      for (int i = 0; i < 16; i++) {
        int r = grp + i * 8;
        int node = min(n0 + r, NN - 1);
        xs[r][c] = g_tow[node * 128 + kc * 32 + c];
      }
#pragma unroll
      for (int j = 0; j < 4; j++) {
        int idx = tid + j * 256, rr = idx >> 5, cc = idx & 31;
        Ws[rr][cc] = lin_w[(kc * 32 + rr) * 128 + oc * 32 + cc];
      }
      __syncthreads();
      tile_mma<32>(&xs[eg][0], &xs[eg+32][0], &xs[eg+64][0], &xs[eg+96][0],
                   &Ws[0][g0], acc);
    }
#pragma unroll
    for (int i = 0; i < 4; i++) {
      int node = n0 + eg + i * 32;
      if (node < NN) {
        float a0, a1, a2, a3;
        unpack2(acc[i][0], a0, a1); unpack2(acc[i][1], a2, a3);
        float4 v;
        v.x = a0 + lin_b[oc*32 + g0 + 0];
        v.y = a1 + lin_b[oc*32 + g0 + 1];
        v.z = a2 + lin_b[oc*32 + g0 + 2];
        v.w = a3 + lin_b[oc*32 + g0 + 3];
        *reinterpret_cast<float4*>(&out[node * 128 + oc * 32 + g0]) = v;
      }
    }
  }
}

// ---- LayerNorm + ReLU + residual -------------------------------------------
__global__ void k_ln(const float* __restrict__ x,
                     const float* __restrict__ g, const float* __restrict__ b,
                     float* __restrict__ out)
{
  int warp = (blockIdx.x * blockDim.x + threadIdx.x) >> 5;
  int lane = threadIdx.x & 31;
  if (warp >= NN) return;
  float4 o = *reinterpret_cast<const float4*>(&out[warp * 128 + lane * 4]);
  float s = o.x + o.y + o.z + o.w;
#pragma unroll
  for (int d = 16; d > 0; d >>= 1) s += __shfl_xor_sync(0xffffffffu, s, d);
  float mu = s * (1.0f / 128.0f);
  float dx = o.x - mu, dy = o.y - mu, dz = o.z - mu, dw = o.w - mu;
  float v = dx*dx + dy*dy + dz*dz + dw*dw;
#pragma unroll
  for (int d = 16; d > 0; d >>= 1) v += __shfl_xor_sync(0xffffffffu, v, d);
  float rstd = rsqrtf(v * (1.0f / 128.0f) + 1e-5f);
  float4 gg = *reinterpret_cast<const float4*>(&g[lane * 4]);
  float4 bb = *reinterpret_cast<const float4*>(&b[lane * 4]);
  float4 xx = *reinterpret_cast<const float4*>(&x[warp * 128 + lane * 4]);
  float4 r;
  r.x = xx.x + fmaxf(dx * rstd * gg.x + bb.x, 0.f);
  r.y = xx.y + fmaxf(dy * rstd * gg.y + bb.y, 0.f);
  r.z = xx.z + fmaxf(dz * rstd * gg.z + bb.z, 0.f);
  r.w = xx.w + fmaxf(dw * rstd * gg.w + bb.w, 0.f);
  *reinterpret_cast<float4*>(&out[warp * 128 + lane * 4]) = r;
}

extern "C" void kernel_launch(void* const* d_in, const int* in_sizes, int n_in,
                              void* d_out, int out_size)
{
  const float* atom_x  = (const float*)d_in[0];
  const int*   bond_x  = (const int*)d_in[1];
  const int*   eidx    = (const int*)d_in[2];
  const int*   mol_deg = (const int*)d_in[3];
  const float* bond_emb= (const float*)d_in[4];
  const float* enc_w   = (const float*)d_in[5];
  const float* enc_b   = (const float*)d_in[6];
  const float* pre_w1  = (const float*)d_in[7];
  const float* pre_b1  = (const float*)d_in[8];
  const float* pre_w2  = (const float*)d_in[9];
  const float* pre_b2  = (const float*)d_in[10];
  const float* post_w1 = (const float*)d_in[11];
  const float* post_b1 = (const float*)d_in[12];
  const float* post_w2 = (const float*)d_in[13];
  const float* post_b2 = (const float*)d_in[14];
  const float* lin_w   = (const float*)d_in[15];
  const float* lin_b   = (const float*)d_in[16];
  const float* ln_g    = (const float*)d_in[17];
  const float* ln_b    = (const float*)d_in[18];
  const int* src = eidx;
  const int* dst = eidx + NE;
  float* out = (float*)d_out;

  size_t esmem = sizeof(EdgeSmem);
  cudaFuncSetAttribute(k_edge, cudaFuncAttributeMaxDynamicSharedMemorySize, (int)esmem);
  cudaFuncSetAttribute(k_scan, cudaFuncAttributeMaxDynamicSharedMemorySize, 20480 * 4);

  k_prep<<<1, 256>>>(mol_deg, bond_emb, enc_w, enc_b);
  k_zero<<<(NN + 255) / 256, 256>>>();
  k_deg<<<NE / 256, 256>>>(dst);
  k_scan<<<1, 1024, 20480 * 4>>>();
  k_fill<<<NE / 256, 256>>>(dst);
  k_edge<<<NE / 128, 256, esmem>>>(atom_x, src, dst, bond_x,
                                   pre_w1, pre_b1, pre_w2, pre_b2);
  k_agg<<<NN, 128>>>();
  k_post<<<(NN + 127) / 128, 256>>>(atom_x, post_w1, post_b1, post_w2, post_b2);
  k_lin<<<(NN + 127) / 128, 256>>>(lin_w, lin_b, out);
  k_ln<<<(NN * 32 + 255) / 256, 256>>>(atom_x, ln_g, ln_b, out);
}

// round 9
// speedup vs baseline: 1.4051x; 1.4051x over previous
#include <cuda_runtime.h>
#include <math.h>

constexpr int NN = 20000;
constexpr int NE = 320000;
constexpr int T = 4;

__device__ float g_m_buf[NE * 128];
__device__ float g_feat[NN * 2048];
__device__ float g_tow[NN * 128];
__device__ int   g_deg[NN];
__device__ int   g_cur[NN];
__device__ int   g_off[NN + 1];
__device__ int   g_slot[NE];
__device__ float g_enc[160];
__device__ float g_avg_log;

// ---- packed fp32x2 helpers ----
__device__ __forceinline__ unsigned long long bcast2(float x) {
  unsigned long long r;
  asm("mov.b64 %0, {%1, %1};" : "=l"(r) : "f"(x));
  return r;
}
__device__ __forceinline__ void fma2(unsigned long long& acc,
                                     unsigned long long a, unsigned long long b) {
  asm("fma.rn.f32x2 %0, %1, %2, %0;" : "+l"(acc) : "l"(a), "l"(b));
}
__device__ __forceinline__ void unpack2(unsigned long long v, float& lo, float& hi) {
  asm("mov.b64 {%0, %1}, %2;" : "=f"(lo), "=f"(hi) : "l"(v));
}

template <int KTOT>
__device__ __forceinline__ void tile_mma(
    const float* __restrict__ h0, const float* __restrict__ h1,
    const float* __restrict__ h2, const float* __restrict__ h3,
    const float* __restrict__ wbase, unsigned long long (&acc)[4][2])
{
  const float* hp[4] = {h0, h1, h2, h3};
#pragma unroll 4
  for (int k = 0; k < KTOT; k += 4) {
    ulonglong2 w[4];
#pragma unroll
    for (int kk = 0; kk < 4; kk++)
      w[kk] = *reinterpret_cast<const ulonglong2*>(wbase + (k + kk) * 32);
#pragma unroll
    for (int i = 0; i < 4; i++) {
      float4 h = *reinterpret_cast<const float4*>(hp[i] + k);
      unsigned long long hx = bcast2(h.x), hy = bcast2(h.y);
      unsigned long long hz = bcast2(h.z), hw = bcast2(h.w);
      fma2(acc[i][0], hx, w[0].x); fma2(acc[i][1], hx, w[0].y);
      fma2(acc[i][0], hy, w[1].x); fma2(acc[i][1], hy, w[1].y);
      fma2(acc[i][0], hz, w[2].x); fma2(acc[i][1], hz, w[2].y);
      fma2(acc[i][0], hw, w[3].x); fma2(acc[i][1], hw, w[3].y);
    }
  }
}

__global__ void k_prep(const int* __restrict__ mol_deg,
                       const float* __restrict__ bond_emb,
                       const float* __restrict__ enc_w,
                       const float* __restrict__ enc_b)
{
  __shared__ float rn[128], rd[128];
  int tid = threadIdx.x;
  if (tid < 128) {
    float dv = (float)mol_deg[tid];
    rn[tid] = logf((float)tid + 1.0f) * dv;
    rd[tid] = dv;
  }
  __syncthreads();
  for (int s = 64; s > 0; s >>= 1) {
    if (tid < s) { rn[tid] += rn[tid + s]; rd[tid] += rd[tid + s]; }
    __syncthreads();
  }
  if (tid == 0) g_avg_log = rn[0] / rd[0];
  if (tid < 160) {
    int bb = tid >> 5, f = tid & 31;
    float a = enc_b[f];
    for (int k = 0; k < 128; k++) a += bond_emb[bb * 128 + k] * enc_w[k * 32 + f];
    g_enc[tid] = a;
  }
}

__global__ void k_zero() {
  int i = blockIdx.x * blockDim.x + threadIdx.x;
  if (i < NN) { g_deg[i] = 0; g_cur[i] = 0; }
}

__global__ void k_deg(const int* __restrict__ dst) {
  int e = blockIdx.x * blockDim.x + threadIdx.x;
  if (e < NE) atomicAdd(&g_deg[dst[e]], 1);
}

// smem-staged coalesced scan: 1024 threads, CH=20
__global__ void k_scan() {
  extern __shared__ int sdeg[];        // 20480 ints
  __shared__ int wsum[32];
  const int tid = threadIdx.x, lane = tid & 31, wid = tid >> 5;
  constexpr int CH = 20;
  for (int j = tid; j < 20480; j += 1024) sdeg[j] = (j < NN) ? g_deg[j] : 0;
  __syncthreads();
  const int base = tid * CH;
  int vals[CH];
  int s = 0;
#pragma unroll
  for (int i = 0; i < CH; i++) { vals[i] = sdeg[base + i]; s += vals[i]; }
  int inc = s;
#pragma unroll
  for (int d = 1; d < 32; d <<= 1) {
    int v = __shfl_up_sync(0xffffffffu, inc, d);
    if (lane >= d) inc += v;
  }
  if (lane == 31) wsum[wid] = inc;
  __syncthreads();
  if (wid == 0) {
    int v = wsum[lane];
    int iv = v;
#pragma unroll
    for (int d = 1; d < 32; d <<= 1) {
      int t2 = __shfl_up_sync(0xffffffffu, iv, d);
      if (lane >= d) iv += t2;
    }
    wsum[lane] = iv - v;
  }
  __syncthreads();
  int run = wsum[wid] + inc - s;
#pragma unroll
  for (int i = 0; i < CH; i++) { sdeg[base + i] = run; run += vals[i]; }
  __syncthreads();
  for (int j = tid; j < NN; j += 1024) g_off[j] = sdeg[j];
  if (tid == 1023) g_off[NN] = run;
}

__global__ void k_fill(const int* __restrict__ dst) {
  int e = blockIdx.x * blockDim.x + threadIdx.x;
  if (e < NE) { int d = dst[e]; g_slot[e] = g_off[d] + atomicAdd(&g_cur[d], 1); }
}

// ---------------- edge pre-MLP: chunked-K, ~55KB smem, 4 CTAs/SM -----------
struct EdgeSmem {
  float hs[128][36];
  float W1s[96][32];
  float W2s[32][32];
  float ms[128][36];
  float enc_s[160];
  int src_s[128], dst_s[128], bond_s[128], slot_s[128];
};

__global__ __launch_bounds__(256) void k_edge(
    const float* __restrict__ x, const int* __restrict__ src,
    const int* __restrict__ dst, const int* __restrict__ bond,
    const float* __restrict__ pre_w1, const float* __restrict__ pre_b1,
    const float* __restrict__ pre_w2, const float* __restrict__ pre_b2)
{
  extern __shared__ __align__(16) char raw[];
  EdgeSmem& s = *reinterpret_cast<EdgeSmem*>(raw);
  const int tid = threadIdx.x, e0 = blockIdx.x * 128;
  if (tid < 128) {
    s.src_s[tid] = src[e0 + tid];
    s.dst_s[tid] = dst[e0 + tid];
    s.bond_s[tid] = bond[e0 + tid];
    s.slot_s[tid] = g_slot[e0 + tid];
  }
  if (tid < 160) s.enc_s[tid] = g_enc[tid];
  const int og = tid & 7, eg = tid >> 3, g0 = og * 4;
  const int c = tid & 31, grp = tid >> 5;

  for (int t = 0; t < T; t++) {
    unsigned long long acc[4][2] = {};
#pragma unroll
    for (int chunk = 0; chunk < 3; chunk++) {
      __syncthreads();                       // hs reuse guard
#pragma unroll
      for (int i = 0; i < 16; i++) {
        int e = grp + i * 8;
        float v;
        if (chunk == 0)      v = x[s.dst_s[e] * 128 + t * 32 + c];
        else if (chunk == 1) v = x[s.src_s[e] * 128 + t * 32 + c];
        else                 v = s.enc_s[s.bond_s[e] * 32 + c];
        s.hs[e][c] = v;
      }
      if (chunk == 0) {
#pragma unroll
        for (int j = 0; j < 12; j++)
          (&s.W1s[0][0])[tid + j * 256] = pre_w1[t * 3072 + tid + j * 256];
#pragma unroll
        for (int j = 0; j < 4; j++)
          (&s.W2s[0][0])[tid + j * 256] = pre_w2[t * 1024 + tid + j * 256];
      }
      __syncthreads();
      tile_mma<32>(&s.hs[eg][0], &s.hs[eg+32][0], &s.hs[eg+64][0], &s.hs[eg+96][0],
                   &s.W1s[chunk * 32][g0], acc);
    }
#pragma unroll
    for (int i = 0; i < 4; i++) {
      float a0, a1, a2, a3;
      unpack2(acc[i][0], a0, a1); unpack2(acc[i][1], a2, a3);
      float4 v;
      v.x = fmaxf(a0 + pre_b1[t*32 + g0 + 0], 0.f);
      v.y = fmaxf(a1 + pre_b1[t*32 + g0 + 1], 0.f);
      v.z = fmaxf(a2 + pre_b1[t*32 + g0 + 2], 0.f);
      v.w = fmaxf(a3 + pre_b1[t*32 + g0 + 3], 0.f);
      *reinterpret_cast<float4*>(&s.ms[eg + i*32][g0]) = v;
    }
    __syncthreads();
    unsigned long long ac2[4][2] = {};
    tile_mma<32>(&s.ms[eg][0], &s.ms[eg+32][0], &s.ms[eg+64][0], &s.ms[eg+96][0],
                 &s.W2s[0][g0], ac2);
#pragma unroll
    for (int i = 0; i < 4; i++) {
      int sl = s.slot_s[eg + i*32];
      float a0, a1, a2, a3;
      unpack2(ac2[i][0], a0, a1); unpack2(ac2[i][1], a2, a3);
      float4 v;
      v.x = a0 + pre_b2[t*32 + g0 + 0];
      v.y = a1 + pre_b2[t*32 + g0 + 1];
      v.z = a2 + pre_b2[t*32 + g0 + 2];
      v.w = a3 + pre_b2[t*32 + g0 + 3];
      *reinterpret_cast<float4*>(&g_m_buf[sl * 128 + t * 32 + g0]) = v;
    }
  }
}

// ---------------- aggregation ----------------------------------------------
__global__ void k_agg(const float* __restrict__ x)
{
  const int n = blockIdx.x, cth = threadIdx.x;
  const int b = g_off[n], d = g_off[n + 1] - b;
  float sum = 0.f, sq = 0.f, mn = 1e30f, mx = -1e30f;
  int i = 0;
  for (; i + 4 <= d; i += 4) {
    float v0 = g_m_buf[(b + i    ) * 128 + cth];
    float v1 = g_m_buf[(b + i + 1) * 128 + cth];
    float v2 = g_m_buf[(b + i + 2) * 128 + cth];
    float v3 = g_m_buf[(b + i + 3) * 128 + cth];
    sum += v0 + v1 + v2 + v3;
    sq += v0*v0 + v1*v1 + v2*v2 + v3*v3;
    mn = fminf(mn, fminf(fminf(v0, v1), fminf(v2, v3)));
    mx = fmaxf(mx, fmaxf(fmaxf(v0, v1), fmaxf(v2, v3)));
  }
  for (; i < d; i++) {
    float v = g_m_buf[(b + i) * 128 + cth];
    sum += v; sq += v * v; mn = fminf(mn, v); mx = fmaxf(mx, v);
  }
  float cnt1 = fmaxf((float)d, 1.f);
  float mean = sum / cnt1;
  float sd = sqrtf(fmaxf(sq / cnt1 - mean * mean, 0.f) + 1e-5f);
  if (d == 0) { mn = 0.f; mx = 0.f; }
  float logd = logf(cnt1 + 1.f), al = g_avg_log;
  float amp = logd / al, att = al / logd;
  int t = cth >> 5, f = cth & 31;
  float* fr = &g_feat[n * 2048 + t * 512];
  fr[f] = x[n * 128 + cth];
  float ag[5] = {sum, mean, mn, mx, sd};
#pragma unroll
  for (int j = 0; j < 5; j++) {
    fr[32  + j * 32 + f] = ag[j];
    fr[192 + j * 32 + f] = ag[j] * amp;
    fr[352 + j * 32 + f] = ag[j] * att;
  }
}

// ---------------- node post-MLP --------------------------------------------
__global__ __launch_bounds__(256) void k_post(
    const float* __restrict__ post_w1, const float* __restrict__ post_b1,
    const float* __restrict__ post_w2, const float* __restrict__ post_b2)
{
  __shared__ __align__(16) float fs[128][36];
  __shared__ __align__(16) float Ws[32][32];
  __shared__ __align__(16) float ms2[128][36];
  const int tid = threadIdx.x, n0 = blockIdx.x * 128;
  const int og = tid & 7, eg = tid >> 3, g0 = og * 4;
  const int c = tid & 31, grp = tid >> 5;

  for (int t = 0; t < T; t++) {
    unsigned long long acc[4][2] = {};
    for (int kc = 0; kc < 16; kc++) {
      __syncthreads();
#pragma unroll
      for (int i = 0; i < 16; i++) {
        int r = grp + i * 8;
        int node = min(n0 + r, NN - 1);
        fs[r][c] = g_feat[node * 2048 + t * 512 + kc * 32 + c];
      }
#pragma unroll
      for (int j = 0; j < 4; j++)
        (&Ws[0][0])[tid + j * 256] = post_w1[t * 16384 + kc * 1024 + tid + j * 256];
      __syncthreads();
      tile_mma<32>(&fs[eg][0], &fs[eg+32][0], &fs[eg+64][0], &fs[eg+96][0],
                   &Ws[0][g0], acc);
    }
#pragma unroll
    for (int i = 0; i < 4; i++) {
      float a0, a1, a2, a3;
      unpack2(acc[i][0], a0, a1); unpack2(acc[i][1], a2, a3);
      float4 v;
      v.x = fmaxf(a0 + post_b1[t*32 + g0 + 0], 0.f);
      v.y = fmaxf(a1 + post_b1[t*32 + g0 + 1], 0.f);
      v.z = fmaxf(a2 + post_b1[t*32 + g0 + 2], 0.f);
      v.w = fmaxf(a3 + post_b1[t*32 + g0 + 3], 0.f);
      *reinterpret_cast<float4*>(&ms2[eg + i*32][g0]) = v;
    }
    __syncthreads();
#pragma unroll
    for (int j = 0; j < 4; j++)
      (&Ws[0][0])[tid + j * 256] = post_w2[t * 1024 + tid + j * 256];
    __syncthreads();
    unsigned long long ac2[4][2] = {};
    tile_mma<32>(&ms2[eg][0], &ms2[eg+32][0], &ms2[eg+64][0], &ms2[eg+96][0],
                 &Ws[0][g0], ac2);
#pragma unroll
    for (int i = 0; i < 4; i++) {
      int node = n0 + eg + i * 32;
      if (node < NN) {
        float a0, a1, a2, a3;
        unpack2(ac2[i][0], a0, a1); unpack2(ac2[i][1], a2, a3);
        float4 v;
        v.x = a0 + post_b2[t*32 + g0 + 0];
        v.y = a1 + post_b2[t*32 + g0 + 1];
        v.z = a2 + post_b2[t*32 + g0 + 2];
        v.w = a3 + post_b2[t*32 + g0 + 3];
        *reinterpret_cast<float4*>(&g_tow[node * 128 + t * 32 + g0]) = v;
      }
    }
    __syncthreads();
  }
}

// ---------------- final 128x128 linear --------------------------------------
__global__ __launch_bounds__(256) void k_lin(
    const float* __restrict__ lin_w, const float* __restrict__ lin_b,
    float* __restrict__ out)
{
  __shared__ __align__(16) float xs[128][36];
  __shared__ __align__(16) float Ws[32][32];
  const int tid = threadIdx.x, n0 = blockIdx.x * 128;
  const int og = tid & 7, eg = tid >> 3, g0 = og * 4;
  const int c = tid & 31, grp = tid >> 5;

  for (int oc = 0; oc < 4; oc++) {
    unsigned long long acc[4][2] = {};
    for (int kc = 0; kc < 4; kc++) {
      __syncthreads();
#pragma unroll
      for (int i = 0; i < 16; i++) {
        int r = grp + i * 8;
        int node = min(n0 + r, NN - 1);
        xs[r][c] = g_tow[node * 128 + kc * 32 + c];
      }
#pragma unroll
      for (int j = 0; j < 4; j++) {
        int idx = tid + j * 256, rr = idx >> 5, cc = idx & 31;
        Ws[rr][cc] = lin_w[(kc * 32 + rr) * 128 + oc * 32 + cc];
      }
      __syncthreads();
      tile_mma<32>(&xs[eg][0], &xs[eg+32][0], &xs[eg+64][0], &xs[eg+96][0],
                   &Ws[0][g0], acc);
    }
#pragma unroll
    for (int i = 0; i < 4; i++) {
      int node = n0 + eg + i * 32;
      if (node < NN) {
        float a0, a1, a2, a3;
        unpack2(acc[i][0], a0, a1); unpack2(acc[i][1], a2, a3);
        float4 v;
        v.x = a0 + lin_b[oc*32 + g0 + 0];
        v.y = a1 + lin_b[oc*32 + g0 + 1];
        v.z = a2 + lin_b[oc*32 + g0 + 2];
        v.w = a3 + lin_b[oc*32 + g0 + 3];
        *reinterpret_cast<float4*>(&out[node * 128 + oc * 32 + g0]) = v;
      }
    }
  }
}

// ---------------- LayerNorm + ReLU + residual -------------------------------
__global__ void k_ln(const float* __restrict__ x,
                     const float* __restrict__ g, const float* __restrict__ b,
                     float* __restrict__ out)
{
  int warp = (blockIdx.x * blockDim.x + threadIdx.x) >> 5;
  int lane = threadIdx.x & 31;
  if (warp >= NN) return;
  float4 o = *reinterpret_cast<const float4*>(&out[warp * 128 + lane * 4]);
  float s = o.x + o.y + o.z + o.w;
#pragma unroll
  for (int d = 16; d > 0; d >>= 1) s += __shfl_xor_sync(0xffffffffu, s, d);
  float mu = s * (1.0f / 128.0f);
  float dx = o.x - mu, dy = o.y - mu, dz = o.z - mu, dw = o.w - mu;
  float v = dx*dx + dy*dy + dz*dz + dw*dw;
#pragma unroll
  for (int d = 16; d > 0; d >>= 1) v += __shfl_xor_sync(0xffffffffu, v, d);
  float rstd = rsqrtf(v * (1.0f / 128.0f) + 1e-5f);
  float4 gg = *reinterpret_cast<const float4*>(&g[lane * 4]);
  float4 bb = *reinterpret_cast<const float4*>(&b[lane * 4]);
  float4 xx = *reinterpret_cast<const float4*>(&x[warp * 128 + lane * 4]);
  float4 r;
  r.x = xx.x + fmaxf(dx * rstd * gg.x + bb.x, 0.f);
  r.y = xx.y + fmaxf(dy * rstd * gg.y + bb.y, 0.f);
  r.z = xx.z + fmaxf(dz * rstd * gg.z + bb.z, 0.f);
  r.w = xx.w + fmaxf(dw * rstd * gg.w + bb.w, 0.f);
  *reinterpret_cast<float4*>(&out[warp * 128 + lane * 4]) = r;
}

extern "C" void kernel_launch(void* const* d_in, const int* in_sizes, int n_in,
                              void* d_out, int out_size)
{
  const float* atom_x  = (const float*)d_in[0];
  const int*   bond_x  = (const int*)d_in[1];
  const int*   eidx    = (const int*)d_in[2];
  const int*   mol_deg = (const int*)d_in[3];
  const float* bond_emb= (const float*)d_in[4];
  const float* enc_w   = (const float*)d_in[5];
  const float* enc_b   = (const float*)d_in[6];
  const float* pre_w1  = (const float*)d_in[7];
  const float* pre_b1  = (const float*)d_in[8];
  const float* pre_w2  = (const float*)d_in[9];
  const float* pre_b2  = (const float*)d_in[10];
  const float* post_w1 = (const float*)d_in[11];
  const float* post_b1 = (const float*)d_in[12];
  const float* post_w2 = (const float*)d_in[13];
  const float* post_b2 = (const float*)d_in[14];
  const float* lin_w   = (const float*)d_in[15];
  const float* lin_b   = (const float*)d_in[16];
  const float* ln_g    = (const float*)d_in[17];
  const float* ln_b    = (const float*)d_in[18];
  const int* src = eidx;
  const int* dst = eidx + NE;
  float* out = (float*)d_out;

  size_t esmem = sizeof(EdgeSmem);
  cudaFuncSetAttribute(k_edge, cudaFuncAttributeMaxDynamicSharedMemorySize, (int)esmem);
  cudaFuncSetAttribute(k_scan, cudaFuncAttributeMaxDynamicSharedMemorySize, 20480 * 4);

  k_prep<<<1, 256>>>(mol_deg, bond_emb, enc_w, enc_b);
  k_zero<<<(NN + 255) / 256, 256>>>();
  k_deg<<<NE / 256, 256>>>(dst);
  k_scan<<<1, 1024, 20480 * 4>>>();
  k_fill<<<NE / 256, 256>>>(dst);
  k_edge<<<NE / 128, 256, esmem>>>(atom_x, src, dst, bond_x,
                                   pre_w1, pre_b1, pre_w2, pre_b2);
  k_agg<<<NN, 128>>>(atom_x);
  k_post<<<(NN + 127) / 128, 256>>>(post_w1, post_b1, post_w2, post_b2);
  k_lin<<<(NN + 127) / 128, 256>>>(lin_w, lin_b, out);
  k_ln<<<(NN * 32 + 255) / 256, 256>>>(atom_x, ln_g, ln_b, out);
}